// round 6
// baseline (speedup 1.0000x reference)
#include <cuda_runtime.h>
#include <cuda_bf16.h>
#include <cstdint>

#define BATCH 2
#define N1 8192
#define CIN 128

// ---------------- scratch (device globals; no allocations allowed) ----------
// cv pyramid stored TRANSPOSED: cvT[b][m][n1]  (m = level point idx, n1 contiguous)
static __device__ float g_cv0[134217728];   // [2][8192][8192]  512 MB
static __device__ float g_cv1[33554432];    // [2][2048][8192]  128 MB
static __device__ float g_cv2[8388608];     // [2][ 512][8192]   32 MB
static __device__ float g_cv3[2097152];     // [2][ 128][8192]    8 MB
#define IDX_CROSS_STRIDE 262144            // 2*8192*16
#define IDX_PYR_BASE     1048576           // 4*262144
#define IDX_PYR1         (IDX_PYR_BASE)
#define IDX_PYR2         (IDX_PYR_BASE + 12288)
#define IDX_PYR3         (IDX_PYR_BASE + 15360)
static __device__ int   g_idx[1048576 + 16128];
static __device__ float g_costs[1048576];   // [2][64][8192]

// bf16 split operands for the tensor-core cost-volume GEMM, layout [b][k][m]
#define FEAT_ELEMS 2097152                 // 2*128*8192
static __device__ __nv_bfloat16 g_f1h[FEAT_ELEMS];
static __device__ __nv_bfloat16 g_f1l[FEAT_ELEMS];
static __device__ __nv_bfloat16 g_f2h[FEAT_ELEMS];   // scaled by 1/128
static __device__ __nv_bfloat16 g_f2l[FEAT_ELEMS];

__device__ __forceinline__ float* cv_ptr(int lvl) {
    switch (lvl) {
        case 0: return g_cv0;
        case 1: return g_cv1;
        case 2: return g_cv2;
        default: return g_cv3;
    }
}

// ---------------- kernel 0: bf16 hi/lo split ---------------------------------
__global__ void __launch_bounds__(256) split_bf16(const float* __restrict__ feat1,
                                                  const float* __restrict__ feat2)
{
    const int i = blockIdx.x * 256 + threadIdx.x;
    if (i >= FEAT_ELEMS) return;
    {
        float a = feat1[i];
        __nv_bfloat16 h = __float2bfloat16_rn(a);
        g_f1h[i] = h;
        g_f1l[i] = __float2bfloat16_rn(a - __bfloat162float(h));
    }
    {
        float a = feat2[i] * 0.0078125f;   // fold 1/128 here (exact pow2 scale)
        __nv_bfloat16 h = __float2bfloat16_rn(a);
        g_f2h[i] = h;
        g_f2l[i] = __float2bfloat16_rn(a - __bfloat162float(h));
    }
}

// ---------------- kernel 1: cost volume GEMM (bf16 split, mma.sync) ----------
// cvT[b][m][n] = sum_c f2s[c][m] * f1[c][n], f2s pre-scaled by 1/128.
// split: x = xh + xl; keep hh + hl + lh terms (drop ll, ~2^-18 relative).
// Double-buffered BK=32 pipeline. mma issue is TERM-OUTER so consecutive
// HMMAs always write different accumulators (no RAW chains).
#define BK 32
#define STAGE_ELEMS 4352          // 32 * 136 (pad 8 -> conflict-free ldmatrix)
#define GEMM_SMEM_BYTES (8 * STAGE_ELEMS * 2)   // 69632 B

__device__ __forceinline__ void cp_async16(void* smem, const void* gmem) {
    unsigned saddr = (unsigned)__cvta_generic_to_shared(smem);
    asm volatile("cp.async.cg.shared.global [%0], [%1], 16;\n" :: "r"(saddr), "l"(gmem));
}
__device__ __forceinline__ void ldsm4t(uint32_t r[4], const __nv_bfloat16* p) {
    unsigned saddr = (unsigned)__cvta_generic_to_shared((void*)p);
    asm volatile("ldmatrix.sync.aligned.m8n8.x4.trans.shared.b16 {%0,%1,%2,%3}, [%4];"
                 : "=r"(r[0]), "=r"(r[1]), "=r"(r[2]), "=r"(r[3]) : "r"(saddr));
}
__device__ __forceinline__ void mma16816(float d[4], const uint32_t a[4], const uint32_t b[2]) {
    asm volatile("mma.sync.aligned.m16n8k16.row.col.f32.bf16.bf16.f32 "
                 "{%0,%1,%2,%3}, {%4,%5,%6,%7}, {%8,%9}, {%0,%1,%2,%3};"
                 : "+f"(d[0]), "+f"(d[1]), "+f"(d[2]), "+f"(d[3])
                 : "r"(a[0]), "r"(a[1]), "r"(a[2]), "r"(a[3]), "r"(b[0]), "r"(b[1]));
}

__global__ void __launch_bounds__(256) gemm_cv_mma()
{
    extern __shared__ __nv_bfloat16 sm[];
    __nv_bfloat16* sAh = sm;                    // [2 stages][32][136]
    __nv_bfloat16* sAl = sm + 2 * STAGE_ELEMS;
    __nv_bfloat16* sBh = sm + 4 * STAGE_ELEMS;
    __nv_bfloat16* sBl = sm + 6 * STAGE_ELEMS;

    const int b  = blockIdx.z;
    const int m0 = blockIdx.y * 128;
    const int n0 = blockIdx.x * 128;
    const int tid  = threadIdx.x;
    const int lane = tid & 31;
    const int warp = tid >> 5;
    const int wm = (warp & 3) * 32;             // 4 warps along m
    const int wn = (warp >> 2) * 64;            // 2 warps along n

    const __nv_bfloat16* gAh = g_f2h + (size_t)b * CIN * 8192 + m0;
    const __nv_bfloat16* gAl = g_f2l + (size_t)b * CIN * 8192 + m0;
    const __nv_bfloat16* gBh = g_f1h + (size_t)b * CIN * 8192 + n0;
    const __nv_bfloat16* gBl = g_f1l + (size_t)b * CIN * 8192 + n0;

    const int l_row0 = tid >> 4;                // 0..15
    const int l_col0 = (tid & 15) * 8;          // 0..120
#define LOAD_STAGE(stg, k0)                                                          \
    {                                                                                \
        _Pragma("unroll")                                                            \
        for (int i = 0; i < 2; i++) {                                                \
            int row = l_row0 + i * 16;                                               \
            size_t gofs = (size_t)((k0) + row) * 8192 + l_col0;                      \
            int sofs = (stg) * STAGE_ELEMS + row * 136 + l_col0;                     \
            cp_async16(sAh + sofs, gAh + gofs);                                      \
            cp_async16(sAl + sofs, gAl + gofs);                                      \
            cp_async16(sBh + sofs, gBh + gofs);                                      \
            cp_async16(sBl + sofs, gBl + gofs);                                      \
        }                                                                            \
        asm volatile("cp.async.commit_group;\n" ::);                                 \
    }

    float acc[2][8][4];
#pragma unroll
    for (int mt = 0; mt < 2; mt++)
#pragma unroll
        for (int j = 0; j < 8; j++)
#pragma unroll
            for (int r = 0; r < 4; r++) acc[mt][j][r] = 0.0f;

    // ldmatrix per-lane offset patterns (element units)
    const int a_row = (lane & 7) + ((lane >> 4) << 3);
    const int a_col = ((lane >> 3) & 1) * 8;
    const int b_row = (lane & 7) + (((lane >> 3) & 1) << 3);
    const int b_col = ((lane >> 4) << 3);

    LOAD_STAGE(0, 0)

    const int NCHUNK = CIN / BK;   // 4
#pragma unroll
    for (int c = 0; c < NCHUNK; c++) {
        if (c + 1 < NCHUNK) {
            LOAD_STAGE((c + 1) & 1, (c + 1) * BK)
            asm volatile("cp.async.wait_group 1;\n" ::);
        } else {
            asm volatile("cp.async.wait_group 0;\n" ::);
        }
        __syncthreads();

        const int stg = (c & 1) * STAGE_ELEMS;
#pragma unroll
        for (int ks = 0; ks < 2; ks++) {
            const int kb = ks * 16;
            uint32_t ah[2][4], al[2][4];
#pragma unroll
            for (int mt = 0; mt < 2; mt++) {
                int ofs = stg + (kb + a_row) * 136 + wm + mt * 16 + a_col;
                ldsm4t(ah[mt], sAh + ofs);
                ldsm4t(al[mt], sAl + ofs);
            }
            uint32_t bh[8][2], bl[8][2];
#pragma unroll
            for (int jp = 0; jp < 4; jp++) {
                int ofs = stg + (kb + b_row) * 136 + wn + jp * 16 + b_col;
                uint32_t r[4];
                ldsm4t(r, sBh + ofs);
                bh[2 * jp][0] = r[0]; bh[2 * jp][1] = r[1];
                bh[2 * jp + 1][0] = r[2]; bh[2 * jp + 1][1] = r[3];
                ldsm4t(r, sBl + ofs);
                bl[2 * jp][0] = r[0]; bl[2 * jp][1] = r[1];
                bl[2 * jp + 1][0] = r[2]; bl[2 * jp + 1][1] = r[3];
            }
            // TERM-OUTER issue order: 16 independent mmas per term, no RAW chains
#pragma unroll
            for (int mt = 0; mt < 2; mt++)
#pragma unroll
                for (int j = 0; j < 8; j++)
                    mma16816(acc[mt][j], ah[mt], bh[j]);   // hh
#pragma unroll
            for (int mt = 0; mt < 2; mt++)
#pragma unroll
                for (int j = 0; j < 8; j++)
                    mma16816(acc[mt][j], ah[mt], bl[j]);   // hl
#pragma unroll
            for (int mt = 0; mt < 2; mt++)
#pragma unroll
                for (int j = 0; j < 8; j++)
                    mma16816(acc[mt][j], al[mt], bh[j]);   // lh
        }
        __syncthreads();
    }

    // epilogue: D frag thread L: g=L>>2, t=L&3
    const int g = lane >> 2;
    const int t = lane & 3;
    float* out = g_cv0 + (size_t)b * 8192 * 8192;
#pragma unroll
    for (int mt = 0; mt < 2; mt++) {
        const int mrow = m0 + wm + mt * 16 + g;
#pragma unroll
        for (int j = 0; j < 8; j++) {
            const int n = n0 + wn + j * 8 + 2 * t;
            float2 v0 = make_float2(acc[mt][j][0], acc[mt][j][1]);
            float2 v1 = make_float2(acc[mt][j][2], acc[mt][j][3]);
            *(float2*)&out[(size_t)mrow * 8192 + n] = v0;
            *(float2*)&out[(size_t)(mrow + 8) * 8192 + n] = v1;
        }
    }
}

// ---------------- kernel 2: warp-per-query brute-force KNN -------------------
template <int K>
__global__ void __launch_bounds__(256) knn_warp(const float* __restrict__ qxyz,
                                                const float* __restrict__ pxyz,
                                                int Nq, int Ni, int out_off)
{
    const int CH = 2048;
    __shared__ float sx[CH], sy[CH], sz[CH];
    const int b    = blockIdx.y;
    const int w    = threadIdx.x >> 5;
    const int lane = threadIdx.x & 31;
    const int qi   = blockIdx.x * 8 + w;

    const float qx = qxyz[(size_t)(b * 3 + 0) * Nq + qi];
    const float qy = qxyz[(size_t)(b * 3 + 1) * Nq + qi];
    const float qz = qxyz[(size_t)(b * 3 + 2) * Nq + qi];
    const float qq = qx * qx + qy * qy + qz * qz;

    float bd[K];
    int   bi[K];
#pragma unroll
    for (int j = 0; j < K; j++) { bd[j] = 1e30f; bi[j] = -(lane + 1); }

    for (int c0 = 0; c0 < Ni; c0 += CH) {
        const int cnt = min(CH, Ni - c0);
        __syncthreads();
        for (int t = threadIdx.x; t < cnt; t += 256) {
            sx[t] = pxyz[(size_t)(b * 3 + 0) * Ni + c0 + t];
            sy[t] = pxyz[(size_t)(b * 3 + 1) * Ni + c0 + t];
            sz[t] = pxyz[(size_t)(b * 3 + 2) * Ni + c0 + t];
        }
        __syncthreads();
        for (int t = lane; t < cnt; t += 32) {
            const float ix = sx[t], iy = sy[t], iz = sz[t];
            const float ii = ix * ix + iy * iy + iz * iz;
            const float d  = qq + ii - 2.0f * (qx * ix + qy * iy + qz * iz);
            if (d < bd[K - 1]) {
                bd[K - 1] = d; bi[K - 1] = c0 + t;
#pragma unroll
                for (int j = K - 1; j > 0; j--) {
                    if (bd[j] < bd[j - 1]) {
                        float td = bd[j]; bd[j] = bd[j - 1]; bd[j - 1] = td;
                        int   ti = bi[j]; bi[j] = bi[j - 1]; bi[j - 1] = ti;
                    }
                }
            }
        }
    }

    // warp merge: extract global top-K from 32 sorted per-lane lists
    int   p   = 0;
    float myd = bd[0];
    int   myi = bi[0];
    int   res = 0;
#pragma unroll
    for (int j = 0; j < K; j++) {
        float d = myd; int ii = myi;
#pragma unroll
        for (int off = 16; off; off >>= 1) {
            float od = __shfl_xor_sync(0xFFFFFFFF, d, off);
            int   oi = __shfl_xor_sync(0xFFFFFFFF, ii, off);
            if (od < d || (od == d && oi < ii)) { d = od; ii = oi; }
        }
        if (lane == j) res = ii;
        if (myi == ii) {
            p++;
            if (p < K) { myd = bd[p]; myi = bi[p]; }
            else       { myd = 1e30f; myi = -(lane + 33); }
        }
    }
    if (lane < K)
        g_idx[out_off + ((size_t)b * Nq + qi) * K + lane] = res;
}

// ---------------- kernel 3: pyramid k=3 average -----------------------------
__global__ void __launch_bounds__(256) pyr_avg(int lvl, int Nm, int Nprev, int idx_off)
{
    const float* prev = cv_ptr(lvl - 1);
    float* out        = cv_ptr(lvl);
    const int b = blockIdx.z;
    const int m = blockIdx.y;
    const int n = blockIdx.x * 256 + threadIdx.x;
    const int* ip = g_idx + idx_off + ((size_t)b * Nm + m) * 3;
    const int i0 = ip[0], i1 = ip[1], i2 = ip[2];
    const float v = prev[((size_t)b * Nprev + i0) * 8192 + n]
                  + prev[((size_t)b * Nprev + i1) * 8192 + n]
                  + prev[((size_t)b * Nprev + i2) * 8192 + n];
    out[((size_t)b * Nm + m) * 8192 + n] = v * (1.0f / 3.0f);
}

// ---------------- kernel 4: per-level matching cost MLP ---------------------
__global__ void __launch_bounds__(128) level_cost(const float* __restrict__ xyz1,
                                                  const float* __restrict__ xyz2,
                                                  int lvl, int Nl,
                                                  const float* __restrict__ w1,
                                                  const float* __restrict__ b1,
                                                  const float* __restrict__ w2,
                                                  const float* __restrict__ b2)
{
    __shared__ float sw1[64], sb1[16], sw2[256], sb2[16];
    const int t = threadIdx.x;
    if (t < 64) sw1[t] = w1[t];
    if (t < 16) sb1[t] = b1[t];
    for (int i = t; i < 256; i += 128) sw2[i] = w2[i];
    if (t >= 64 && t < 80) sb2[t - 64] = b2[t - 64];
    __syncthreads();

    const int b = blockIdx.y;
    const int n = blockIdx.x * 128 + t;
    const float* cvT = cv_ptr(lvl);
    const int* ip = g_idx + (size_t)lvl * IDX_CROSS_STRIDE + ((size_t)b * N1 + n) * 16;

    const float px = xyz1[(size_t)(b * 3 + 0) * N1 + n];
    const float py = xyz1[(size_t)(b * 3 + 1) * N1 + n];
    const float pz = xyz1[(size_t)(b * 3 + 2) * N1 + n];

    float acc[16];
#pragma unroll
    for (int o = 0; o < 16; o++) acc[o] = 0.0f;

#pragma unroll 4
    for (int k = 0; k < 16; k++) {
        const int i = ip[k];
        const float dx = xyz2[(size_t)(b * 3 + 0) * Nl + i] - px;
        const float dy = xyz2[(size_t)(b * 3 + 1) * Nl + i] - py;
        const float dz = xyz2[(size_t)(b * 3 + 2) * Nl + i] - pz;
        const float corr = cvT[((size_t)b * Nl + i) * 8192 + n];

        float h1[16];
#pragma unroll
        for (int o = 0; o < 16; o++) {
            float a = fmaf(sw1[o * 4 + 0], dx, sb1[o]);
            a = fmaf(sw1[o * 4 + 1], dy, a);
            a = fmaf(sw1[o * 4 + 2], dz, a);
            a = fmaf(sw1[o * 4 + 3], corr, a);
            h1[o] = fmaxf(a, 0.0f);
        }
#pragma unroll
        for (int o2 = 0; o2 < 16; o2++) {
            float a = sb2[o2];
#pragma unroll
            for (int o = 0; o < 16; o++) a = fmaf(sw2[o2 * 16 + o], h1[o], a);
            acc[o2] += fmaxf(a, 0.0f);
        }
    }
#pragma unroll
    for (int o2 = 0; o2 < 16; o2++)
        g_costs[((size_t)b * 64 + lvl * 16 + o2) * N1 + n] = acc[o2];
}

// ---------------- kernel 5: final 64x64 MLP ---------------------------------
__global__ void __launch_bounds__(256) final_mlp(const float* __restrict__ wm,
                                                 const float* __restrict__ bm,
                                                 float* __restrict__ out)
{
    __shared__ float swm[4096];
    __shared__ float sbm[64];
    const int t = threadIdx.x;
    for (int i = t; i < 4096; i += 256) swm[i] = wm[i];
    if (t < 64) sbm[t] = bm[t];
    __syncthreads();

    const int b = blockIdx.y;
    const int n = blockIdx.x * 256 + t;

    float c[64];
#pragma unroll
    for (int cc = 0; cc < 64; cc++)
        c[cc] = g_costs[((size_t)b * 64 + cc) * N1 + n];

#pragma unroll 4
    for (int o = 0; o < 64; o++) {
        float a = sbm[o];
#pragma unroll
        for (int cc = 0; cc < 64; cc++)
            a = fmaf(swm[o * 64 + cc], c[cc], a);
        out[((size_t)b * 64 + o) * N1 + n] = fmaxf(a, 0.0f);
    }
}

// ---------------- launcher ---------------------------------------------------
extern "C" void kernel_launch(void* const* d_in, const int* in_sizes, int n_in,
                              void* d_out, int out_size)
{
    const float* xyz1   = (const float*)d_in[0];
    const float* xyz2_0 = (const float*)d_in[1];
    const float* xyz2_1 = (const float*)d_in[2];
    const float* xyz2_2 = (const float*)d_in[3];
    const float* xyz2_3 = (const float*)d_in[4];
    const float* feat1  = (const float*)d_in[5];
    const float* feat2  = (const float*)d_in[6];
    const float* w1 = (const float*)d_in[7];
    const float* b1 = (const float*)d_in[8];
    const float* w2 = (const float*)d_in[9];
    const float* b2 = (const float*)d_in[10];
    const float* wm = (const float*)d_in[11];
    const float* bm = (const float*)d_in[12];
    float* out = (float*)d_out;

    static bool smem_set = false;
    if (!smem_set) {
        cudaFuncSetAttribute(gemm_cv_mma, cudaFuncAttributeMaxDynamicSharedMemorySize,
                             GEMM_SMEM_BYTES);
        smem_set = true;
    }

    // Launch order puts gemm_cv_mma at position 6 so ncu (-s 5 -c 1) profiles it.
    // 1) bf16 hi/lo split of features
    split_bf16<<<FEAT_ELEMS / 256, 256>>>(feat1, feat2);

    // 2-4) pyramid KNN (k=3) — xyz-only deps
    knn_warp<3><<<dim3(2048 / 8, 2), 256>>>(xyz2_1, xyz2_0, 2048, 8192, IDX_PYR1);
    knn_warp<3><<<dim3( 512 / 8, 2), 256>>>(xyz2_2, xyz2_1,  512, 2048, IDX_PYR2);
    knn_warp<3><<<dim3( 128 / 8, 2), 256>>>(xyz2_3, xyz2_2,  128,  512, IDX_PYR3);

    // 5) cross KNN level 3 (xyz-only dep)
    knn_warp<16><<<dim3(N1 / 8, 2), 256>>>(xyz1, xyz2_3, N1,  128, 3 * IDX_CROSS_STRIDE);

    // 6) cost volume GEMM  <-- profiled launch
    gemm_cv_mma<<<dim3(64, 64, 2), 256, GEMM_SMEM_BYTES>>>();

    // 7-9) remaining cross KNN
    knn_warp<16><<<dim3(N1 / 8, 2), 256>>>(xyz1, xyz2_0, N1, 8192, 0 * IDX_CROSS_STRIDE);
    knn_warp<16><<<dim3(N1 / 8, 2), 256>>>(xyz1, xyz2_1, N1, 2048, 1 * IDX_CROSS_STRIDE);
    knn_warp<16><<<dim3(N1 / 8, 2), 256>>>(xyz1, xyz2_2, N1,  512, 2 * IDX_CROSS_STRIDE);

    // 10-12) pyramid averaging
    pyr_avg<<<dim3(32, 2048, 2), 256>>>(1, 2048, 8192, IDX_PYR1);
    pyr_avg<<<dim3(32,  512, 2), 256>>>(2,  512, 2048, IDX_PYR2);
    pyr_avg<<<dim3(32,  128, 2), 256>>>(3,  128,  512, IDX_PYR3);

    // 13-16) per-level matching cost MLPs
    level_cost<<<dim3(64, 2), 128>>>(xyz1, xyz2_0, 0, 8192, w1, b1, w2, b2);
    level_cost<<<dim3(64, 2), 128>>>(xyz1, xyz2_1, 1, 2048, w1, b1, w2, b2);
    level_cost<<<dim3(64, 2), 128>>>(xyz1, xyz2_2, 2,  512, w1, b1, w2, b2);
    level_cost<<<dim3(64, 2), 128>>>(xyz1, xyz2_3, 3,  128, w1, b1, w2, b2);

    // 17) final MLP -> output [2][64][8192]
    final_mlp<<<dim3(32, 2), 256>>>(wm, bm, out);
}

// round 8
// speedup vs baseline: 1.5198x; 1.5198x over previous
#include <cuda_runtime.h>
#include <cuda_bf16.h>
#include <cstdint>

#define BATCH 2
#define N1 8192
#define CIN 128

// ---------------- scratch (device globals; no allocations allowed) ----------
// cv pyramid stored TRANSPOSED: cvT[b][m][n1]  (m = level point idx, n1 contiguous)
static __device__ float g_cv0[134217728];   // [2][8192][8192]  512 MB
static __device__ float g_cv1[33554432];    // [2][2048][8192]  128 MB
static __device__ float g_cv2[8388608];     // [2][ 512][8192]   32 MB
static __device__ float g_cv3[2097152];     // [2][ 128][8192]    8 MB
#define IDX_CROSS_STRIDE 262144            // 2*8192*16
#define IDX_PYR_BASE     1048576           // 4*262144
#define IDX_PYR1         (IDX_PYR_BASE)
#define IDX_PYR2         (IDX_PYR_BASE + 12288)
#define IDX_PYR3         (IDX_PYR_BASE + 15360)
static __device__ int   g_idx[1048576 + 16128];
static __device__ float g_costs[1048576];   // [2][64][8192]

// bf16 split operands for the tensor-core cost-volume GEMM, layout [b][k][m]
#define FEAT_ELEMS 2097152                 // 2*128*8192
static __device__ __nv_bfloat16 g_f1h[FEAT_ELEMS];
static __device__ __nv_bfloat16 g_f1l[FEAT_ELEMS];
static __device__ __nv_bfloat16 g_f2h[FEAT_ELEMS];   // scaled by 1/128
static __device__ __nv_bfloat16 g_f2l[FEAT_ELEMS];

__device__ __forceinline__ float* cv_ptr(int lvl) {
    switch (lvl) {
        case 0: return g_cv0;
        case 1: return g_cv1;
        case 2: return g_cv2;
        default: return g_cv3;
    }
}

// ---------------- kernel 0: bf16 hi/lo split ---------------------------------
__global__ void __launch_bounds__(256) split_bf16(const float* __restrict__ feat1,
                                                  const float* __restrict__ feat2)
{
    const int i = blockIdx.x * 256 + threadIdx.x;
    if (i >= FEAT_ELEMS) return;
    {
        float a = feat1[i];
        __nv_bfloat16 h = __float2bfloat16_rn(a);
        g_f1h[i] = h;
        g_f1l[i] = __float2bfloat16_rn(a - __bfloat162float(h));
    }
    {
        float a = feat2[i] * 0.0078125f;   // fold 1/128 here (exact pow2 scale)
        __nv_bfloat16 h = __float2bfloat16_rn(a);
        g_f2h[i] = h;
        g_f2l[i] = __float2bfloat16_rn(a - __bfloat162float(h));
    }
}

// ---------------- kernel 1: cost volume GEMM (bf16 split, mma.sync) ----------
// EXACT round-2 configuration (best measured): double-buffered BK=32,
// B fragments staged up-front, interleaved hh/hl/lh issue.
#define BK 32
#define STAGE_ELEMS 4352          // 32 * 136 (pad 8 -> conflict-free ldmatrix)
#define GEMM_SMEM_BYTES (8 * STAGE_ELEMS * 2)   // 69632 B

__device__ __forceinline__ void cp_async16(void* smem, const void* gmem) {
    unsigned saddr = (unsigned)__cvta_generic_to_shared(smem);
    asm volatile("cp.async.cg.shared.global [%0], [%1], 16;\n" :: "r"(saddr), "l"(gmem));
}
__device__ __forceinline__ void ldsm4t(uint32_t r[4], const __nv_bfloat16* p) {
    unsigned saddr = (unsigned)__cvta_generic_to_shared((void*)p);
    asm volatile("ldmatrix.sync.aligned.m8n8.x4.trans.shared.b16 {%0,%1,%2,%3}, [%4];"
                 : "=r"(r[0]), "=r"(r[1]), "=r"(r[2]), "=r"(r[3]) : "r"(saddr));
}
__device__ __forceinline__ void mma16816(float d[4], const uint32_t a[4], const uint32_t b[2]) {
    asm volatile("mma.sync.aligned.m16n8k16.row.col.f32.bf16.bf16.f32 "
                 "{%0,%1,%2,%3}, {%4,%5,%6,%7}, {%8,%9}, {%0,%1,%2,%3};"
                 : "+f"(d[0]), "+f"(d[1]), "+f"(d[2]), "+f"(d[3])
                 : "r"(a[0]), "r"(a[1]), "r"(a[2]), "r"(a[3]), "r"(b[0]), "r"(b[1]));
}

__global__ void __launch_bounds__(256) gemm_cv_mma()
{
    extern __shared__ __nv_bfloat16 sm[];
    __nv_bfloat16* sAh = sm;                    // [2 stages][32][136]
    __nv_bfloat16* sAl = sm + 2 * STAGE_ELEMS;
    __nv_bfloat16* sBh = sm + 4 * STAGE_ELEMS;
    __nv_bfloat16* sBl = sm + 6 * STAGE_ELEMS;

    const int b  = blockIdx.z;
    const int m0 = blockIdx.y * 128;
    const int n0 = blockIdx.x * 128;
    const int tid  = threadIdx.x;
    const int lane = tid & 31;
    const int warp = tid >> 5;
    const int wm = (warp & 3) * 32;             // 4 warps along m
    const int wn = (warp >> 2) * 64;            // 2 warps along n

    const __nv_bfloat16* gAh = g_f2h + (size_t)b * CIN * 8192 + m0;
    const __nv_bfloat16* gAl = g_f2l + (size_t)b * CIN * 8192 + m0;
    const __nv_bfloat16* gBh = g_f1h + (size_t)b * CIN * 8192 + n0;
    const __nv_bfloat16* gBl = g_f1l + (size_t)b * CIN * 8192 + n0;

    const int l_row0 = tid >> 4;                // 0..15
    const int l_col0 = (tid & 15) * 8;          // 0..120
#define LOAD_STAGE(stg, k0)                                                          \
    {                                                                                \
        _Pragma("unroll")                                                            \
        for (int i = 0; i < 2; i++) {                                                \
            int row = l_row0 + i * 16;                                               \
            size_t gofs = (size_t)((k0) + row) * 8192 + l_col0;                      \
            int sofs = (stg) * STAGE_ELEMS + row * 136 + l_col0;                     \
            cp_async16(sAh + sofs, gAh + gofs);                                      \
            cp_async16(sAl + sofs, gAl + gofs);                                      \
            cp_async16(sBh + sofs, gBh + gofs);                                      \
            cp_async16(sBl + sofs, gBl + gofs);                                      \
        }                                                                            \
        asm volatile("cp.async.commit_group;\n" ::);                                 \
    }

    float acc[2][8][4];
#pragma unroll
    for (int mt = 0; mt < 2; mt++)
#pragma unroll
        for (int j = 0; j < 8; j++)
#pragma unroll
            for (int r = 0; r < 4; r++) acc[mt][j][r] = 0.0f;

    // ldmatrix per-lane offset patterns (element units)
    const int a_row = (lane & 7) + ((lane >> 4) << 3);
    const int a_col = ((lane >> 3) & 1) * 8;
    const int b_row = (lane & 7) + (((lane >> 3) & 1) << 3);
    const int b_col = ((lane >> 4) << 3);

    LOAD_STAGE(0, 0)

    const int NCHUNK = CIN / BK;   // 4
#pragma unroll
    for (int c = 0; c < NCHUNK; c++) {
        if (c + 1 < NCHUNK) {
            LOAD_STAGE((c + 1) & 1, (c + 1) * BK)
            asm volatile("cp.async.wait_group 1;\n" ::);
        } else {
            asm volatile("cp.async.wait_group 0;\n" ::);
        }
        __syncthreads();

        const int stg = (c & 1) * STAGE_ELEMS;
#pragma unroll
        for (int ks = 0; ks < 2; ks++) {
            const int kb = ks * 16;
            uint32_t ah[2][4], al[2][4];
#pragma unroll
            for (int mt = 0; mt < 2; mt++) {
                int ofs = stg + (kb + a_row) * 136 + wm + mt * 16 + a_col;
                ldsm4t(ah[mt], sAh + ofs);
                ldsm4t(al[mt], sAl + ofs);
            }
            uint32_t bh[8][2], bl[8][2];
#pragma unroll
            for (int jp = 0; jp < 4; jp++) {
                int ofs = stg + (kb + b_row) * 136 + wn + jp * 16 + b_col;
                uint32_t r[4];
                ldsm4t(r, sBh + ofs);
                bh[2 * jp][0] = r[0]; bh[2 * jp][1] = r[1];
                bh[2 * jp + 1][0] = r[2]; bh[2 * jp + 1][1] = r[3];
                ldsm4t(r, sBl + ofs);
                bl[2 * jp][0] = r[0]; bl[2 * jp][1] = r[1];
                bl[2 * jp + 1][0] = r[2]; bl[2 * jp + 1][1] = r[3];
            }
#pragma unroll
            for (int mt = 0; mt < 2; mt++)
#pragma unroll
                for (int j = 0; j < 8; j++) {
                    mma16816(acc[mt][j], ah[mt], bh[j]);   // hh
                    mma16816(acc[mt][j], ah[mt], bl[j]);   // hl
                    mma16816(acc[mt][j], al[mt], bh[j]);   // lh
                }
        }
        __syncthreads();
    }

    // epilogue: D frag thread L: g=L>>2, t=L&3
    const int g = lane >> 2;
    const int t = lane & 3;
    float* out = g_cv0 + (size_t)b * 8192 * 8192;
#pragma unroll
    for (int mt = 0; mt < 2; mt++) {
        const int mrow = m0 + wm + mt * 16 + g;
#pragma unroll
        for (int j = 0; j < 8; j++) {
            const int n = n0 + wn + j * 8 + 2 * t;
            float2 v0 = make_float2(acc[mt][j][0], acc[mt][j][1]);
            float2 v1 = make_float2(acc[mt][j][2], acc[mt][j][3]);
            *(float2*)&out[(size_t)mrow * 8192 + n] = v0;
            *(float2*)&out[(size_t)(mrow + 8) * 8192 + n] = v1;
        }
    }
}

// ---------------- kernel 2a: thread-per-query KNN (K=16; R2 version) ---------
// Warp-level insertion is too divergent at K=16; thread-per-query wins there.
template <int K>
__global__ void __launch_bounds__(128) knn_thread(const float* __restrict__ qxyz,
                                                  const float* __restrict__ pxyz,
                                                  int Nq, int Ni, int out_off)
{
    const int CH = 1024;
    __shared__ float sx[CH], sy[CH], sz[CH];
    const int b  = blockIdx.y;
    const int qi = blockIdx.x * 128 + threadIdx.x;

    const float qx = qxyz[(size_t)(b * 3 + 0) * Nq + qi];
    const float qy = qxyz[(size_t)(b * 3 + 1) * Nq + qi];
    const float qz = qxyz[(size_t)(b * 3 + 2) * Nq + qi];
    const float qq = qx * qx + qy * qy + qz * qz;

    float bd[K];
    int   bi[K];
#pragma unroll
    for (int j = 0; j < K; j++) { bd[j] = 1e30f; bi[j] = 0; }

    for (int c0 = 0; c0 < Ni; c0 += CH) {
        const int cnt = min(CH, Ni - c0);
        for (int t = threadIdx.x; t < cnt; t += 128) {
            sx[t] = pxyz[(size_t)(b * 3 + 0) * Ni + c0 + t];
            sy[t] = pxyz[(size_t)(b * 3 + 1) * Ni + c0 + t];
            sz[t] = pxyz[(size_t)(b * 3 + 2) * Ni + c0 + t];
        }
        __syncthreads();
        for (int t = 0; t < cnt; t++) {
            const float ix = sx[t], iy = sy[t], iz = sz[t];
            const float ii = ix * ix + iy * iy + iz * iz;
            const float d  = qq + ii - 2.0f * (qx * ix + qy * iy + qz * iz);
            if (d < bd[K - 1]) {
                bd[K - 1] = d; bi[K - 1] = c0 + t;
#pragma unroll
                for (int j = K - 1; j > 0; j--) {
                    if (bd[j] < bd[j - 1]) {
                        float td = bd[j]; bd[j] = bd[j - 1]; bd[j - 1] = td;
                        int   ti = bi[j]; bi[j] = bi[j - 1]; bi[j - 1] = ti;
                    }
                }
            }
        }
        __syncthreads();
    }

    int* out = g_idx + out_off;
#pragma unroll
    for (int j = 0; j < K; j++)
        out[((size_t)b * Nq + qi) * K + j] = bi[j];
}

// ---------------- kernel 2b: warp-per-query KNN (K=3; measured win) ----------
template <int K>
__global__ void __launch_bounds__(256) knn_warp(const float* __restrict__ qxyz,
                                                const float* __restrict__ pxyz,
                                                int Nq, int Ni, int out_off)
{
    const int CH = 2048;
    __shared__ float sx[CH], sy[CH], sz[CH];
    const int b    = blockIdx.y;
    const int w    = threadIdx.x >> 5;
    const int lane = threadIdx.x & 31;
    const int qi   = blockIdx.x * 8 + w;

    const float qx = qxyz[(size_t)(b * 3 + 0) * Nq + qi];
    const float qy = qxyz[(size_t)(b * 3 + 1) * Nq + qi];
    const float qz = qxyz[(size_t)(b * 3 + 2) * Nq + qi];
    const float qq = qx * qx + qy * qy + qz * qz;

    float bd[K];
    int   bi[K];
#pragma unroll
    for (int j = 0; j < K; j++) { bd[j] = 1e30f; bi[j] = -(lane + 1); }

    for (int c0 = 0; c0 < Ni; c0 += CH) {
        const int cnt = min(CH, Ni - c0);
        __syncthreads();
        for (int t = threadIdx.x; t < cnt; t += 256) {
            sx[t] = pxyz[(size_t)(b * 3 + 0) * Ni + c0 + t];
            sy[t] = pxyz[(size_t)(b * 3 + 1) * Ni + c0 + t];
            sz[t] = pxyz[(size_t)(b * 3 + 2) * Ni + c0 + t];
        }
        __syncthreads();
        for (int t = lane; t < cnt; t += 32) {
            const float ix = sx[t], iy = sy[t], iz = sz[t];
            const float ii = ix * ix + iy * iy + iz * iz;
            const float d  = qq + ii - 2.0f * (qx * ix + qy * iy + qz * iz);
            if (d < bd[K - 1]) {
                bd[K - 1] = d; bi[K - 1] = c0 + t;
#pragma unroll
                for (int j = K - 1; j > 0; j--) {
                    if (bd[j] < bd[j - 1]) {
                        float td = bd[j]; bd[j] = bd[j - 1]; bd[j - 1] = td;
                        int   ti = bi[j]; bi[j] = bi[j - 1]; bi[j - 1] = ti;
                    }
                }
            }
        }
    }

    // warp merge: extract global top-K from 32 sorted per-lane lists
    int   p   = 0;
    float myd = bd[0];
    int   myi = bi[0];
    int   res = 0;
#pragma unroll
    for (int j = 0; j < K; j++) {
        float d = myd; int ii = myi;
#pragma unroll
        for (int off = 16; off; off >>= 1) {
            float od = __shfl_xor_sync(0xFFFFFFFF, d, off);
            int   oi = __shfl_xor_sync(0xFFFFFFFF, ii, off);
            if (od < d || (od == d && oi < ii)) { d = od; ii = oi; }
        }
        if (lane == j) res = ii;
        if (myi == ii) {
            p++;
            if (p < K) { myd = bd[p]; myi = bi[p]; }
            else       { myd = 1e30f; myi = -(lane + 33); }
        }
    }
    if (lane < K)
        g_idx[out_off + ((size_t)b * Nq + qi) * K + lane] = res;
}

// ---------------- kernel 3: pyramid k=3 average -----------------------------
__global__ void __launch_bounds__(256) pyr_avg(int lvl, int Nm, int Nprev, int idx_off)
{
    const float* prev = cv_ptr(lvl - 1);
    float* out        = cv_ptr(lvl);
    const int b = blockIdx.z;
    const int m = blockIdx.y;
    const int n = blockIdx.x * 256 + threadIdx.x;
    const int* ip = g_idx + idx_off + ((size_t)b * Nm + m) * 3;
    const int i0 = ip[0], i1 = ip[1], i2 = ip[2];
    const float v = prev[((size_t)b * Nprev + i0) * 8192 + n]
                  + prev[((size_t)b * Nprev + i1) * 8192 + n]
                  + prev[((size_t)b * Nprev + i2) * 8192 + n];
    out[((size_t)b * Nm + m) * 8192 + n] = v * (1.0f / 3.0f);
}

// ---------------- kernel 4: per-level matching cost MLP ---------------------
__global__ void __launch_bounds__(128) level_cost(const float* __restrict__ xyz1,
                                                  const float* __restrict__ xyz2,
                                                  int lvl, int Nl,
                                                  const float* __restrict__ w1,
                                                  const float* __restrict__ b1,
                                                  const float* __restrict__ w2,
                                                  const float* __restrict__ b2)
{
    __shared__ float sw1[64], sb1[16], sw2[256], sb2[16];
    const int t = threadIdx.x;
    if (t < 64) sw1[t] = w1[t];
    if (t < 16) sb1[t] = b1[t];
    for (int i = t; i < 256; i += 128) sw2[i] = w2[i];
    if (t >= 64 && t < 80) sb2[t - 64] = b2[t - 64];
    __syncthreads();

    const int b = blockIdx.y;
    const int n = blockIdx.x * 128 + t;
    const float* cvT = cv_ptr(lvl);
    const int* ip = g_idx + (size_t)lvl * IDX_CROSS_STRIDE + ((size_t)b * N1 + n) * 16;

    const float px = xyz1[(size_t)(b * 3 + 0) * N1 + n];
    const float py = xyz1[(size_t)(b * 3 + 1) * N1 + n];
    const float pz = xyz1[(size_t)(b * 3 + 2) * N1 + n];

    float acc[16];
#pragma unroll
    for (int o = 0; o < 16; o++) acc[o] = 0.0f;

#pragma unroll 4
    for (int k = 0; k < 16; k++) {
        const int i = ip[k];
        const float dx = xyz2[(size_t)(b * 3 + 0) * Nl + i] - px;
        const float dy = xyz2[(size_t)(b * 3 + 1) * Nl + i] - py;
        const float dz = xyz2[(size_t)(b * 3 + 2) * Nl + i] - pz;
        const float corr = cvT[((size_t)b * Nl + i) * 8192 + n];

        float h1[16];
#pragma unroll
        for (int o = 0; o < 16; o++) {
            float a = fmaf(sw1[o * 4 + 0], dx, sb1[o]);
            a = fmaf(sw1[o * 4 + 1], dy, a);
            a = fmaf(sw1[o * 4 + 2], dz, a);
            a = fmaf(sw1[o * 4 + 3], corr, a);
            h1[o] = fmaxf(a, 0.0f);
        }
#pragma unroll
        for (int o2 = 0; o2 < 16; o2++) {
            float a = sb2[o2];
#pragma unroll
            for (int o = 0; o < 16; o++) a = fmaf(sw2[o2 * 16 + o], h1[o], a);
            acc[o2] += fmaxf(a, 0.0f);
        }
    }
#pragma unroll
    for (int o2 = 0; o2 < 16; o2++)
        g_costs[((size_t)b * 64 + lvl * 16 + o2) * N1 + n] = acc[o2];
}

// ---------------- kernel 5: final 64x64 MLP ---------------------------------
__global__ void __launch_bounds__(256) final_mlp(const float* __restrict__ wm,
                                                 const float* __restrict__ bm,
                                                 float* __restrict__ out)
{
    __shared__ float swm[4096];
    __shared__ float sbm[64];
    const int t = threadIdx.x;
    for (int i = t; i < 4096; i += 256) swm[i] = wm[i];
    if (t < 64) sbm[t] = bm[t];
    __syncthreads();

    const int b = blockIdx.y;
    const int n = blockIdx.x * 256 + t;

    float c[64];
#pragma unroll
    for (int cc = 0; cc < 64; cc++)
        c[cc] = g_costs[((size_t)b * 64 + cc) * N1 + n];

#pragma unroll 4
    for (int o = 0; o < 64; o++) {
        float a = sbm[o];
#pragma unroll
        for (int cc = 0; cc < 64; cc++)
            a = fmaf(swm[o * 64 + cc], c[cc], a);
        out[((size_t)b * 64 + o) * N1 + n] = fmaxf(a, 0.0f);
    }
}

// ---------------- launcher ---------------------------------------------------
extern "C" void kernel_launch(void* const* d_in, const int* in_sizes, int n_in,
                              void* d_out, int out_size)
{
    const float* xyz1   = (const float*)d_in[0];
    const float* xyz2_0 = (const float*)d_in[1];
    const float* xyz2_1 = (const float*)d_in[2];
    const float* xyz2_2 = (const float*)d_in[3];
    const float* xyz2_3 = (const float*)d_in[4];
    const float* feat1  = (const float*)d_in[5];
    const float* feat2  = (const float*)d_in[6];
    const float* w1 = (const float*)d_in[7];
    const float* b1 = (const float*)d_in[8];
    const float* w2 = (const float*)d_in[9];
    const float* b2 = (const float*)d_in[10];
    const float* wm = (const float*)d_in[11];
    const float* bm = (const float*)d_in[12];
    float* out = (float*)d_out;

    static bool smem_set = false;
    if (!smem_set) {
        cudaFuncSetAttribute(gemm_cv_mma, cudaFuncAttributeMaxDynamicSharedMemorySize,
                             GEMM_SMEM_BYTES);
        smem_set = true;
    }

    // ncu captures the 4th launch -> put the GEMM there.
    // 1) bf16 hi/lo split of features
    split_bf16<<<FEAT_ELEMS / 256, 256>>>(feat1, feat2);

    // 2-3) pyramid KNN (k=3) levels 1-2 — xyz-only deps
    knn_warp<3><<<dim3(2048 / 8, 2), 256>>>(xyz2_1, xyz2_0, 2048, 8192, IDX_PYR1);
    knn_warp<3><<<dim3( 512 / 8, 2), 256>>>(xyz2_2, xyz2_1,  512, 2048, IDX_PYR2);

    // 4) cost volume GEMM  <-- profiled launch
    gemm_cv_mma<<<dim3(64, 64, 2), 256, GEMM_SMEM_BYTES>>>();

    // 5) pyramid KNN level 3
    knn_warp<3><<<dim3( 128 / 8, 2), 256>>>(xyz2_3, xyz2_2,  128,  512, IDX_PYR3);

    // 6-9) cross KNN (k=16), thread-per-query (R2 version)
    knn_thread<16><<<dim3(64, 2), 128>>>(xyz1, xyz2_0, N1, 8192, 0 * IDX_CROSS_STRIDE);
    knn_thread<16><<<dim3(64, 2), 128>>>(xyz1, xyz2_1, N1, 2048, 1 * IDX_CROSS_STRIDE);
    knn_thread<16><<<dim3(64, 2), 128>>>(xyz1, xyz2_2, N1,  512, 2 * IDX_CROSS_STRIDE);
    knn_thread<16><<<dim3(64, 2), 128>>>(xyz1, xyz2_3, N1,  128, 3 * IDX_CROSS_STRIDE);

    // 10-12) pyramid averaging
    pyr_avg<<<dim3(32, 2048, 2), 256>>>(1, 2048, 8192, IDX_PYR1);
    pyr_avg<<<dim3(32,  512, 2), 256>>>(2,  512, 2048, IDX_PYR2);
    pyr_avg<<<dim3(32,  128, 2), 256>>>(3,  128,  512, IDX_PYR3);

    // 13-16) per-level matching cost MLPs
    level_cost<<<dim3(64, 2), 128>>>(xyz1, xyz2_0, 0, 8192, w1, b1, w2, b2);
    level_cost<<<dim3(64, 2), 128>>>(xyz1, xyz2_1, 1, 2048, w1, b1, w2, b2);
    level_cost<<<dim3(64, 2), 128>>>(xyz1, xyz2_2, 2,  512, w1, b1, w2, b2);
    level_cost<<<dim3(64, 2), 128>>>(xyz1, xyz2_3, 3,  128, w1, b1, w2, b2);

    // 17) final MLP -> output [2][64][8192]
    final_mlp<<<dim3(32, 2), 256>>>(wm, bm, out);
}

// round 9
// speedup vs baseline: 2.3755x; 1.5630x over previous
#include <cuda_runtime.h>
#include <cuda_bf16.h>
#include <cstdint>

#define BATCH 2
#define N1 8192
#define CIN 128

// ---------------- scratch (device globals; no allocations allowed) ----------
static __device__ float g_cv0[134217728];   // [2][8192][8192]  512 MB
static __device__ float g_cv1[33554432];    // [2][2048][8192]  128 MB
static __device__ float g_cv2[8388608];     // [2][ 512][8192]   32 MB
static __device__ float g_cv3[2097152];     // [2][ 128][8192]    8 MB
#define IDX_CROSS_STRIDE 262144            // 2*8192*16
#define IDX_PYR_BASE     1048576           // 4*262144
#define IDX_PYR1         (IDX_PYR_BASE)
#define IDX_PYR2         (IDX_PYR_BASE + 12288)
#define IDX_PYR3         (IDX_PYR_BASE + 15360)
static __device__ int   g_idx[1048576 + 16128];
static __device__ float g_costs[1048576];   // [2][64][8192]

// bf16 split operands for the tensor-core cost-volume GEMM, layout [b][k][m]
#define FEAT_ELEMS 2097152                 // 2*128*8192
static __device__ __nv_bfloat16 g_f1h[FEAT_ELEMS];
static __device__ __nv_bfloat16 g_f1l[FEAT_ELEMS];
static __device__ __nv_bfloat16 g_f2h[FEAT_ELEMS];   // scaled by 1/128
static __device__ __nv_bfloat16 g_f2l[FEAT_ELEMS];

__device__ __forceinline__ float* cv_ptr(int lvl) {
    switch (lvl) {
        case 0: return g_cv0;
        case 1: return g_cv1;
        case 2: return g_cv2;
        default: return g_cv3;
    }
}

// ---------------- kernel 0: bf16 hi/lo split ---------------------------------
__global__ void __launch_bounds__(256) split_bf16(const float* __restrict__ feat1,
                                                  const float* __restrict__ feat2)
{
    const int i = blockIdx.x * 256 + threadIdx.x;
    if (i >= FEAT_ELEMS) return;
    {
        float a = feat1[i];
        __nv_bfloat16 h = __float2bfloat16_rn(a);
        g_f1h[i] = h;
        g_f1l[i] = __float2bfloat16_rn(a - __bfloat162float(h));
    }
    {
        float a = feat2[i] * 0.0078125f;   // fold 1/128 (exact pow2)
        __nv_bfloat16 h = __float2bfloat16_rn(a);
        g_f2h[i] = h;
        g_f2l[i] = __float2bfloat16_rn(a - __bfloat162float(h));
    }
}

// ---------------- kernel 1: cost volume GEMM (UNCHANGED from R8 win) ---------
#define BK 32
#define STAGE_ELEMS 4352          // 32 * 136 (pad 8 -> conflict-free ldmatrix)
#define GEMM_SMEM_BYTES (8 * STAGE_ELEMS * 2)   // 69632 B

__device__ __forceinline__ void cp_async16(void* smem, const void* gmem) {
    unsigned saddr = (unsigned)__cvta_generic_to_shared(smem);
    asm volatile("cp.async.cg.shared.global [%0], [%1], 16;\n" :: "r"(saddr), "l"(gmem));
}
__device__ __forceinline__ void ldsm4t(uint32_t r[4], const __nv_bfloat16* p) {
    unsigned saddr = (unsigned)__cvta_generic_to_shared((void*)p);
    asm volatile("ldmatrix.sync.aligned.m8n8.x4.trans.shared.b16 {%0,%1,%2,%3}, [%4];"
                 : "=r"(r[0]), "=r"(r[1]), "=r"(r[2]), "=r"(r[3]) : "r"(saddr));
}
__device__ __forceinline__ void mma16816(float d[4], const uint32_t a[4], const uint32_t b[2]) {
    asm volatile("mma.sync.aligned.m16n8k16.row.col.f32.bf16.bf16.f32 "
                 "{%0,%1,%2,%3}, {%4,%5,%6,%7}, {%8,%9}, {%0,%1,%2,%3};"
                 : "+f"(d[0]), "+f"(d[1]), "+f"(d[2]), "+f"(d[3])
                 : "r"(a[0]), "r"(a[1]), "r"(a[2]), "r"(a[3]), "r"(b[0]), "r"(b[1]));
}

__global__ void __launch_bounds__(256) gemm_cv_mma()
{
    extern __shared__ __nv_bfloat16 sm[];
    __nv_bfloat16* sAh = sm;                    // [2 stages][32][136]
    __nv_bfloat16* sAl = sm + 2 * STAGE_ELEMS;
    __nv_bfloat16* sBh = sm + 4 * STAGE_ELEMS;
    __nv_bfloat16* sBl = sm + 6 * STAGE_ELEMS;

    const int b  = blockIdx.z;
    const int m0 = blockIdx.y * 128;
    const int n0 = blockIdx.x * 128;
    const int tid  = threadIdx.x;
    const int lane = tid & 31;
    const int warp = tid >> 5;
    const int wm = (warp & 3) * 32;
    const int wn = (warp >> 2) * 64;

    const __nv_bfloat16* gAh = g_f2h + (size_t)b * CIN * 8192 + m0;
    const __nv_bfloat16* gAl = g_f2l + (size_t)b * CIN * 8192 + m0;
    const __nv_bfloat16* gBh = g_f1h + (size_t)b * CIN * 8192 + n0;
    const __nv_bfloat16* gBl = g_f1l + (size_t)b * CIN * 8192 + n0;

    const int l_row0 = tid >> 4;
    const int l_col0 = (tid & 15) * 8;
#define LOAD_STAGE(stg, k0)                                                          \
    {                                                                                \
        _Pragma("unroll")                                                            \
        for (int i = 0; i < 2; i++) {                                                \
            int row = l_row0 + i * 16;                                               \
            size_t gofs = (size_t)((k0) + row) * 8192 + l_col0;                      \
            int sofs = (stg) * STAGE_ELEMS + row * 136 + l_col0;                     \
            cp_async16(sAh + sofs, gAh + gofs);                                      \
            cp_async16(sAl + sofs, gAl + gofs);                                      \
            cp_async16(sBh + sofs, gBh + gofs);                                      \
            cp_async16(sBl + sofs, gBl + gofs);                                      \
        }                                                                            \
        asm volatile("cp.async.commit_group;\n" ::);                                 \
    }

    float acc[2][8][4];
#pragma unroll
    for (int mt = 0; mt < 2; mt++)
#pragma unroll
        for (int j = 0; j < 8; j++)
#pragma unroll
            for (int r = 0; r < 4; r++) acc[mt][j][r] = 0.0f;

    const int a_row = (lane & 7) + ((lane >> 4) << 3);
    const int a_col = ((lane >> 3) & 1) * 8;
    const int b_row = (lane & 7) + (((lane >> 3) & 1) << 3);
    const int b_col = ((lane >> 4) << 3);

    LOAD_STAGE(0, 0)

    const int NCHUNK = CIN / BK;   // 4
#pragma unroll
    for (int c = 0; c < NCHUNK; c++) {
        if (c + 1 < NCHUNK) {
            LOAD_STAGE((c + 1) & 1, (c + 1) * BK)
            asm volatile("cp.async.wait_group 1;\n" ::);
        } else {
            asm volatile("cp.async.wait_group 0;\n" ::);
        }
        __syncthreads();

        const int stg = (c & 1) * STAGE_ELEMS;
#pragma unroll
        for (int ks = 0; ks < 2; ks++) {
            const int kb = ks * 16;
            uint32_t ah[2][4], al[2][4];
#pragma unroll
            for (int mt = 0; mt < 2; mt++) {
                int ofs = stg + (kb + a_row) * 136 + wm + mt * 16 + a_col;
                ldsm4t(ah[mt], sAh + ofs);
                ldsm4t(al[mt], sAl + ofs);
            }
            uint32_t bh[8][2], bl[8][2];
#pragma unroll
            for (int jp = 0; jp < 4; jp++) {
                int ofs = stg + (kb + b_row) * 136 + wn + jp * 16 + b_col;
                uint32_t r[4];
                ldsm4t(r, sBh + ofs);
                bh[2 * jp][0] = r[0]; bh[2 * jp][1] = r[1];
                bh[2 * jp + 1][0] = r[2]; bh[2 * jp + 1][1] = r[3];
                ldsm4t(r, sBl + ofs);
                bl[2 * jp][0] = r[0]; bl[2 * jp][1] = r[1];
                bl[2 * jp + 1][0] = r[2]; bl[2 * jp + 1][1] = r[3];
            }
#pragma unroll
            for (int mt = 0; mt < 2; mt++)
#pragma unroll
                for (int j = 0; j < 8; j++) {
                    mma16816(acc[mt][j], ah[mt], bh[j]);   // hh
                    mma16816(acc[mt][j], ah[mt], bl[j]);   // hl
                    mma16816(acc[mt][j], al[mt], bh[j]);   // lh
                }
        }
        __syncthreads();
    }

    const int g = lane >> 2;
    const int t = lane & 3;
    float* out = g_cv0 + (size_t)b * 8192 * 8192;
#pragma unroll
    for (int mt = 0; mt < 2; mt++) {
        const int mrow = m0 + wm + mt * 16 + g;
#pragma unroll
        for (int j = 0; j < 8; j++) {
            const int n = n0 + wn + j * 8 + 2 * t;
            float2 v0 = make_float2(acc[mt][j][0], acc[mt][j][1]);
            float2 v1 = make_float2(acc[mt][j][2], acc[mt][j][3]);
            *(float2*)&out[(size_t)mrow * 8192 + n] = v0;
            *(float2*)&out[(size_t)(mrow + 8) * 8192 + n] = v1;
        }
    }
}

// ---------------- kernel 2a: FUSED thread-per-query KNN16, all 4 levels ------
__global__ void __launch_bounds__(128) knn16_all(const float* __restrict__ xyz1,
                                                 const float* __restrict__ x0,
                                                 const float* __restrict__ x1,
                                                 const float* __restrict__ x2,
                                                 const float* __restrict__ x3)
{
    const int l = blockIdx.z;
    const float* pxyz = (l == 0) ? x0 : (l == 1) ? x1 : (l == 2) ? x2 : x3;
    const int Ni      = (l == 0) ? 8192 : (l == 1) ? 2048 : (l == 2) ? 512 : 128;
    const int out_off = l * IDX_CROSS_STRIDE;
    const int Nq = N1;

    const int CH = 1024;
    __shared__ float sx[CH], sy[CH], sz[CH];
    const int b  = blockIdx.y;
    const int qi = blockIdx.x * 128 + threadIdx.x;

    const float qx = xyz1[(size_t)(b * 3 + 0) * Nq + qi];
    const float qy = xyz1[(size_t)(b * 3 + 1) * Nq + qi];
    const float qz = xyz1[(size_t)(b * 3 + 2) * Nq + qi];
    const float qq = qx * qx + qy * qy + qz * qz;

    float bd[16];
    int   bi[16];
#pragma unroll
    for (int j = 0; j < 16; j++) { bd[j] = 1e30f; bi[j] = 0; }

    for (int c0 = 0; c0 < Ni; c0 += CH) {
        const int cnt = min(CH, Ni - c0);
        for (int t = threadIdx.x; t < cnt; t += 128) {
            sx[t] = pxyz[(size_t)(b * 3 + 0) * Ni + c0 + t];
            sy[t] = pxyz[(size_t)(b * 3 + 1) * Ni + c0 + t];
            sz[t] = pxyz[(size_t)(b * 3 + 2) * Ni + c0 + t];
        }
        __syncthreads();
        for (int t = 0; t < cnt; t++) {
            const float ix = sx[t], iy = sy[t], iz = sz[t];
            const float ii = ix * ix + iy * iy + iz * iz;
            const float d  = qq + ii - 2.0f * (qx * ix + qy * iy + qz * iz);
            if (d < bd[15]) {
                bd[15] = d; bi[15] = c0 + t;
#pragma unroll
                for (int j = 15; j > 0; j--) {
                    if (bd[j] < bd[j - 1]) {
                        float td = bd[j]; bd[j] = bd[j - 1]; bd[j - 1] = td;
                        int   ti = bi[j]; bi[j] = bi[j - 1]; bi[j - 1] = ti;
                    }
                }
            }
        }
        __syncthreads();
    }

    int* out = g_idx + out_off;
#pragma unroll
    for (int j = 0; j < 16; j++)
        out[((size_t)b * Nq + qi) * 16 + j] = bi[j];
}

// ---------------- kernel 2b: FUSED warp-per-query KNN3, all 3 levels ---------
__global__ void __launch_bounds__(256) knn3_all(const float* __restrict__ x0,
                                                const float* __restrict__ x1,
                                                const float* __restrict__ x2,
                                                const float* __restrict__ x3)
{
    const int l = blockIdx.z;
    const float* qxyz; const float* pxyz; int Nq, Ni, out_off;
    if (l == 0)      { qxyz = x1; pxyz = x0; Nq = 2048; Ni = 8192; out_off = IDX_PYR1; }
    else if (l == 1) { qxyz = x2; pxyz = x1; Nq = 512;  Ni = 2048; out_off = IDX_PYR2; }
    else             { qxyz = x3; pxyz = x2; Nq = 128;  Ni = 512;  out_off = IDX_PYR3; }
    if (blockIdx.x * 8 >= Nq) return;   // uniform per block: safe w.r.t. barriers

    const int CH = 2048;
    __shared__ float sx[CH], sy[CH], sz[CH];
    const int b    = blockIdx.y;
    const int w    = threadIdx.x >> 5;
    const int lane = threadIdx.x & 31;
    const int qi   = blockIdx.x * 8 + w;

    const float qx = qxyz[(size_t)(b * 3 + 0) * Nq + qi];
    const float qy = qxyz[(size_t)(b * 3 + 1) * Nq + qi];
    const float qz = qxyz[(size_t)(b * 3 + 2) * Nq + qi];
    const float qq = qx * qx + qy * qy + qz * qz;

    float bd[3];
    int   bi[3];
#pragma unroll
    for (int j = 0; j < 3; j++) { bd[j] = 1e30f; bi[j] = -(lane + 1); }

    for (int c0 = 0; c0 < Ni; c0 += CH) {
        const int cnt = min(CH, Ni - c0);
        __syncthreads();
        for (int t = threadIdx.x; t < cnt; t += 256) {
            sx[t] = pxyz[(size_t)(b * 3 + 0) * Ni + c0 + t];
            sy[t] = pxyz[(size_t)(b * 3 + 1) * Ni + c0 + t];
            sz[t] = pxyz[(size_t)(b * 3 + 2) * Ni + c0 + t];
        }
        __syncthreads();
        for (int t = lane; t < cnt; t += 32) {
            const float ix = sx[t], iy = sy[t], iz = sz[t];
            const float ii = ix * ix + iy * iy + iz * iz;
            const float d  = qq + ii - 2.0f * (qx * ix + qy * iy + qz * iz);
            if (d < bd[2]) {
                bd[2] = d; bi[2] = c0 + t;
#pragma unroll
                for (int j = 2; j > 0; j--) {
                    if (bd[j] < bd[j - 1]) {
                        float td = bd[j]; bd[j] = bd[j - 1]; bd[j - 1] = td;
                        int   ti = bi[j]; bi[j] = bi[j - 1]; bi[j - 1] = ti;
                    }
                }
            }
        }
    }

    int   p   = 0;
    float myd = bd[0];
    int   myi = bi[0];
    int   res = 0;
#pragma unroll
    for (int j = 0; j < 3; j++) {
        float d = myd; int ii = myi;
#pragma unroll
        for (int off = 16; off; off >>= 1) {
            float od = __shfl_xor_sync(0xFFFFFFFF, d, off);
            int   oi = __shfl_xor_sync(0xFFFFFFFF, ii, off);
            if (od < d || (od == d && oi < ii)) { d = od; ii = oi; }
        }
        if (lane == j) res = ii;
        if (myi == ii) {
            p++;
            if (p < 3) { myd = bd[p]; myi = bi[p]; }
            else       { myd = 1e30f; myi = -(lane + 33); }
        }
    }
    if (lane < 3)
        g_idx[out_off + ((size_t)b * Nq + qi) * 3 + lane] = res;
}

// ---------------- kernel 3: pyramid k=3 average -----------------------------
__global__ void __launch_bounds__(256) pyr_avg(int lvl, int Nm, int Nprev, int idx_off)
{
    const float* prev = cv_ptr(lvl - 1);
    float* out        = cv_ptr(lvl);
    const int b = blockIdx.z;
    const int m = blockIdx.y;
    const int n = blockIdx.x * 256 + threadIdx.x;
    const int* ip = g_idx + idx_off + ((size_t)b * Nm + m) * 3;
    const int i0 = ip[0], i1 = ip[1], i2 = ip[2];
    const float v = prev[((size_t)b * Nprev + i0) * 8192 + n]
                  + prev[((size_t)b * Nprev + i1) * 8192 + n]
                  + prev[((size_t)b * Nprev + i2) * 8192 + n];
    out[((size_t)b * Nm + m) * 8192 + n] = v * (1.0f / 3.0f);
}

// ---------------- kernel 4: FUSED per-level matching cost MLP ----------------
__global__ void __launch_bounds__(128) lc_all(const float* __restrict__ xyz1,
                                              const float* __restrict__ x0,
                                              const float* __restrict__ x1,
                                              const float* __restrict__ x2,
                                              const float* __restrict__ x3,
                                              const float* __restrict__ w1,
                                              const float* __restrict__ b1,
                                              const float* __restrict__ w2,
                                              const float* __restrict__ b2)
{
    __shared__ float sw1[64], sb1[16], sw2[256], sb2[16];
    const int t = threadIdx.x;
    if (t < 64) sw1[t] = w1[t];
    if (t < 16) sb1[t] = b1[t];
    for (int i = t; i < 256; i += 128) sw2[i] = w2[i];
    if (t >= 64 && t < 80) sb2[t - 64] = b2[t - 64];
    __syncthreads();

    const int lvl = blockIdx.z;
    const float* xyz2 = (lvl == 0) ? x0 : (lvl == 1) ? x1 : (lvl == 2) ? x2 : x3;
    const int Nl      = (lvl == 0) ? 8192 : (lvl == 1) ? 2048 : (lvl == 2) ? 512 : 128;

    const int b = blockIdx.y;
    const int n = blockIdx.x * 128 + t;
    const float* cvT = cv_ptr(lvl);
    const int* ip = g_idx + (size_t)lvl * IDX_CROSS_STRIDE + ((size_t)b * N1 + n) * 16;

    const float px = xyz1[(size_t)(b * 3 + 0) * N1 + n];
    const float py = xyz1[(size_t)(b * 3 + 1) * N1 + n];
    const float pz = xyz1[(size_t)(b * 3 + 2) * N1 + n];

    float acc[16];
#pragma unroll
    for (int o = 0; o < 16; o++) acc[o] = 0.0f;

#pragma unroll 4
    for (int k = 0; k < 16; k++) {
        const int i = ip[k];
        const float dx = xyz2[(size_t)(b * 3 + 0) * Nl + i] - px;
        const float dy = xyz2[(size_t)(b * 3 + 1) * Nl + i] - py;
        const float dz = xyz2[(size_t)(b * 3 + 2) * Nl + i] - pz;
        const float corr = cvT[((size_t)b * Nl + i) * 8192 + n];

        float h1[16];
#pragma unroll
        for (int o = 0; o < 16; o++) {
            float a = fmaf(sw1[o * 4 + 0], dx, sb1[o]);
            a = fmaf(sw1[o * 4 + 1], dy, a);
            a = fmaf(sw1[o * 4 + 2], dz, a);
            a = fmaf(sw1[o * 4 + 3], corr, a);
            h1[o] = fmaxf(a, 0.0f);
        }
#pragma unroll
        for (int o2 = 0; o2 < 16; o2++) {
            float a = sb2[o2];
#pragma unroll
            for (int o = 0; o < 16; o++) a = fmaf(sw2[o2 * 16 + o], h1[o], a);
            acc[o2] += fmaxf(a, 0.0f);
        }
    }
#pragma unroll
    for (int o2 = 0; o2 < 16; o2++)
        g_costs[((size_t)b * 64 + lvl * 16 + o2) * N1 + n] = acc[o2];
}

// ---------------- kernel 5: final 64x64 MLP ---------------------------------
__global__ void __launch_bounds__(256) final_mlp(const float* __restrict__ wm,
                                                 const float* __restrict__ bm,
                                                 float* __restrict__ out)
{
    __shared__ float swm[4096];
    __shared__ float sbm[64];
    const int t = threadIdx.x;
    for (int i = t; i < 4096; i += 256) swm[i] = wm[i];
    if (t < 64) sbm[t] = bm[t];
    __syncthreads();

    const int b = blockIdx.y;
    const int n = blockIdx.x * 256 + t;

    float c[64];
#pragma unroll
    for (int cc = 0; cc < 64; cc++)
        c[cc] = g_costs[((size_t)b * 64 + cc) * N1 + n];

#pragma unroll 4
    for (int o = 0; o < 64; o++) {
        float a = sbm[o];
#pragma unroll
        for (int cc = 0; cc < 64; cc++)
            a = fmaf(swm[o * 64 + cc], c[cc], a);
        out[((size_t)b * 64 + o) * N1 + n] = fmaxf(a, 0.0f);
    }
}

// ---------------- launcher ---------------------------------------------------
extern "C" void kernel_launch(void* const* d_in, const int* in_sizes, int n_in,
                              void* d_out, int out_size)
{
    const float* xyz1   = (const float*)d_in[0];
    const float* xyz2_0 = (const float*)d_in[1];
    const float* xyz2_1 = (const float*)d_in[2];
    const float* xyz2_2 = (const float*)d_in[3];
    const float* xyz2_3 = (const float*)d_in[4];
    const float* feat1  = (const float*)d_in[5];
    const float* feat2  = (const float*)d_in[6];
    const float* w1 = (const float*)d_in[7];
    const float* b1 = (const float*)d_in[8];
    const float* w2 = (const float*)d_in[9];
    const float* b2 = (const float*)d_in[10];
    const float* wm = (const float*)d_in[11];
    const float* bm = (const float*)d_in[12];
    float* out = (float*)d_out;

    static bool init = false;
    static cudaStream_t s1, s2;
    static cudaEvent_t ev0, evK3, evK16;
    if (!init) {
        cudaFuncSetAttribute(gemm_cv_mma, cudaFuncAttributeMaxDynamicSharedMemorySize,
                             GEMM_SMEM_BYTES);
        cudaStreamCreateWithFlags(&s1, cudaStreamNonBlocking);
        cudaStreamCreateWithFlags(&s2, cudaStreamNonBlocking);
        cudaEventCreateWithFlags(&ev0,  cudaEventDisableTiming);
        cudaEventCreateWithFlags(&evK3, cudaEventDisableTiming);
        cudaEventCreateWithFlags(&evK16, cudaEventDisableTiming);
        init = true;
    }

    // ---- fork: knn work runs concurrently with split+gemm ----
    cudaEventRecord(ev0, 0);
    cudaStreamWaitEvent(s1, ev0, 0);
    cudaStreamWaitEvent(s2, ev0, 0);

    // s1: pyramid KNN (all 3 levels fused)
    knn3_all<<<dim3(256, 2, 3), 256, 0, s1>>>(xyz2_0, xyz2_1, xyz2_2, xyz2_3);
    cudaEventRecord(evK3, s1);

    // s2: cross KNN (all 4 levels fused)
    knn16_all<<<dim3(64, 2, 4), 128, 0, s2>>>(xyz1, xyz2_0, xyz2_1, xyz2_2, xyz2_3);
    cudaEventRecord(evK16, s2);

    // default stream: split -> gemm
    split_bf16<<<FEAT_ELEMS / 256, 256>>>(feat1, feat2);
    gemm_cv_mma<<<dim3(64, 64, 2), 256, GEMM_SMEM_BYTES>>>();

    // ---- join s1: pyramid averaging needs cv0 + pyramid knn ----
    cudaStreamWaitEvent(0, evK3, 0);
    pyr_avg<<<dim3(32, 2048, 2), 256>>>(1, 2048, 8192, IDX_PYR1);
    pyr_avg<<<dim3(32,  512, 2), 256>>>(2,  512, 2048, IDX_PYR2);
    pyr_avg<<<dim3(32,  128, 2), 256>>>(3,  128,  512, IDX_PYR3);

    // ---- join s2: matching cost needs cross knn + all cv levels ----
    cudaStreamWaitEvent(0, evK16, 0);
    lc_all<<<dim3(64, 2, 4), 128>>>(xyz1, xyz2_0, xyz2_1, xyz2_2, xyz2_3,
                                    w1, b1, w2, b2);

    // final MLP -> output [2][64][8192]
    final_mlp<<<dim3(32, 2), 256>>>(wm, bm, out);
}

// round 10
// speedup vs baseline: 2.5359x; 1.0676x over previous
#include <cuda_runtime.h>
#include <cuda_bf16.h>
#include <cstdint>

#define BATCH 2
#define N1 8192
#define CIN 128

// ---------------- scratch (device globals; no allocations allowed) ----------
static __device__ float g_cv0[134217728];   // [2][8192][8192]  512 MB
static __device__ float g_cv1[33554432];    // [2][2048][8192]  128 MB
static __device__ float g_cv2[8388608];     // [2][ 512][8192]   32 MB
static __device__ float g_cv3[2097152];     // [2][ 128][8192]    8 MB
#define IDX_CROSS_STRIDE 262144            // 2*8192*16
#define IDX_PYR_BASE     1048576           // 4*262144
#define IDX_PYR1         (IDX_PYR_BASE)
#define IDX_PYR2         (IDX_PYR_BASE + 12288)
#define IDX_PYR3         (IDX_PYR_BASE + 15360)
static __device__ int   g_idx[1048576 + 16128];
static __device__ float g_costs[1048576];   // [2][64][8192]

// knn16 chunked-scan scratch: [lvl][b][query][chunk*16 + j]
#define KNN_SCR_ELEMS (4 * 2 * 8192 * 64)
static __device__ float g_scr_d[KNN_SCR_ELEMS];
static __device__ int   g_scr_i[KNN_SCR_ELEMS];

// bf16 split operands for the tensor-core cost-volume GEMM, layout [b][k][m]
#define FEAT_ELEMS 2097152                 // 2*128*8192
static __device__ __nv_bfloat16 g_f1h[FEAT_ELEMS];
static __device__ __nv_bfloat16 g_f1l[FEAT_ELEMS];
static __device__ __nv_bfloat16 g_f2h[FEAT_ELEMS];   // scaled by 1/128
static __device__ __nv_bfloat16 g_f2l[FEAT_ELEMS];

__device__ __forceinline__ float* cv_ptr(int lvl) {
    switch (lvl) {
        case 0: return g_cv0;
        case 1: return g_cv1;
        case 2: return g_cv2;
        default: return g_cv3;
    }
}

// ---------------- kernel 0: bf16 hi/lo split ---------------------------------
__global__ void __launch_bounds__(256) split_bf16(const float* __restrict__ feat1,
                                                  const float* __restrict__ feat2)
{
    const int i = blockIdx.x * 256 + threadIdx.x;
    if (i >= FEAT_ELEMS) return;
    {
        float a = feat1[i];
        __nv_bfloat16 h = __float2bfloat16_rn(a);
        g_f1h[i] = h;
        g_f1l[i] = __float2bfloat16_rn(a - __bfloat162float(h));
    }
    {
        float a = feat2[i] * 0.0078125f;   // fold 1/128 (exact pow2)
        __nv_bfloat16 h = __float2bfloat16_rn(a);
        g_f2h[i] = h;
        g_f2l[i] = __float2bfloat16_rn(a - __bfloat162float(h));
    }
}

// ---------------- kernel 1: cost volume GEMM (UNCHANGED from R8/R9 win) ------
#define BK 32
#define STAGE_ELEMS 4352          // 32 * 136 (pad 8 -> conflict-free ldmatrix)
#define GEMM_SMEM_BYTES (8 * STAGE_ELEMS * 2)   // 69632 B

__device__ __forceinline__ void cp_async16(void* smem, const void* gmem) {
    unsigned saddr = (unsigned)__cvta_generic_to_shared(smem);
    asm volatile("cp.async.cg.shared.global [%0], [%1], 16;\n" :: "r"(saddr), "l"(gmem));
}
__device__ __forceinline__ void ldsm4t(uint32_t r[4], const __nv_bfloat16* p) {
    unsigned saddr = (unsigned)__cvta_generic_to_shared((void*)p);
    asm volatile("ldmatrix.sync.aligned.m8n8.x4.trans.shared.b16 {%0,%1,%2,%3}, [%4];"
                 : "=r"(r[0]), "=r"(r[1]), "=r"(r[2]), "=r"(r[3]) : "r"(saddr));
}
__device__ __forceinline__ void mma16816(float d[4], const uint32_t a[4], const uint32_t b[2]) {
    asm volatile("mma.sync.aligned.m16n8k16.row.col.f32.bf16.bf16.f32 "
                 "{%0,%1,%2,%3}, {%4,%5,%6,%7}, {%8,%9}, {%0,%1,%2,%3};"
                 : "+f"(d[0]), "+f"(d[1]), "+f"(d[2]), "+f"(d[3])
                 : "r"(a[0]), "r"(a[1]), "r"(a[2]), "r"(a[3]), "r"(b[0]), "r"(b[1]));
}

__global__ void __launch_bounds__(256) gemm_cv_mma()
{
    extern __shared__ __nv_bfloat16 sm[];
    __nv_bfloat16* sAh = sm;                    // [2 stages][32][136]
    __nv_bfloat16* sAl = sm + 2 * STAGE_ELEMS;
    __nv_bfloat16* sBh = sm + 4 * STAGE_ELEMS;
    __nv_bfloat16* sBl = sm + 6 * STAGE_ELEMS;

    const int b  = blockIdx.z;
    const int m0 = blockIdx.y * 128;
    const int n0 = blockIdx.x * 128;
    const int tid  = threadIdx.x;
    const int lane = tid & 31;
    const int warp = tid >> 5;
    const int wm = (warp & 3) * 32;
    const int wn = (warp >> 2) * 64;

    const __nv_bfloat16* gAh = g_f2h + (size_t)b * CIN * 8192 + m0;
    const __nv_bfloat16* gAl = g_f2l + (size_t)b * CIN * 8192 + m0;
    const __nv_bfloat16* gBh = g_f1h + (size_t)b * CIN * 8192 + n0;
    const __nv_bfloat16* gBl = g_f1l + (size_t)b * CIN * 8192 + n0;

    const int l_row0 = tid >> 4;
    const int l_col0 = (tid & 15) * 8;
#define LOAD_STAGE(stg, k0)                                                          \
    {                                                                                \
        _Pragma("unroll")                                                            \
        for (int i = 0; i < 2; i++) {                                                \
            int row = l_row0 + i * 16;                                               \
            size_t gofs = (size_t)((k0) + row) * 8192 + l_col0;                      \
            int sofs = (stg) * STAGE_ELEMS + row * 136 + l_col0;                     \
            cp_async16(sAh + sofs, gAh + gofs);                                      \
            cp_async16(sAl + sofs, gAl + gofs);                                      \
            cp_async16(sBh + sofs, gBh + gofs);                                      \
            cp_async16(sBl + sofs, gBl + gofs);                                      \
        }                                                                            \
        asm volatile("cp.async.commit_group;\n" ::);                                 \
    }

    float acc[2][8][4];
#pragma unroll
    for (int mt = 0; mt < 2; mt++)
#pragma unroll
        for (int j = 0; j < 8; j++)
#pragma unroll
            for (int r = 0; r < 4; r++) acc[mt][j][r] = 0.0f;

    const int a_row = (lane & 7) + ((lane >> 4) << 3);
    const int a_col = ((lane >> 3) & 1) * 8;
    const int b_row = (lane & 7) + (((lane >> 3) & 1) << 3);
    const int b_col = ((lane >> 4) << 3);

    LOAD_STAGE(0, 0)

    const int NCHUNK = CIN / BK;   // 4
#pragma unroll
    for (int c = 0; c < NCHUNK; c++) {
        if (c + 1 < NCHUNK) {
            LOAD_STAGE((c + 1) & 1, (c + 1) * BK)
            asm volatile("cp.async.wait_group 1;\n" ::);
        } else {
            asm volatile("cp.async.wait_group 0;\n" ::);
        }
        __syncthreads();

        const int stg = (c & 1) * STAGE_ELEMS;
#pragma unroll
        for (int ks = 0; ks < 2; ks++) {
            const int kb = ks * 16;
            uint32_t ah[2][4], al[2][4];
#pragma unroll
            for (int mt = 0; mt < 2; mt++) {
                int ofs = stg + (kb + a_row) * 136 + wm + mt * 16 + a_col;
                ldsm4t(ah[mt], sAh + ofs);
                ldsm4t(al[mt], sAl + ofs);
            }
            uint32_t bh[8][2], bl[8][2];
#pragma unroll
            for (int jp = 0; jp < 4; jp++) {
                int ofs = stg + (kb + b_row) * 136 + wn + jp * 16 + b_col;
                uint32_t r[4];
                ldsm4t(r, sBh + ofs);
                bh[2 * jp][0] = r[0]; bh[2 * jp][1] = r[1];
                bh[2 * jp + 1][0] = r[2]; bh[2 * jp + 1][1] = r[3];
                ldsm4t(r, sBl + ofs);
                bl[2 * jp][0] = r[0]; bl[2 * jp][1] = r[1];
                bl[2 * jp + 1][0] = r[2]; bl[2 * jp + 1][1] = r[3];
            }
#pragma unroll
            for (int mt = 0; mt < 2; mt++)
#pragma unroll
                for (int j = 0; j < 8; j++) {
                    mma16816(acc[mt][j], ah[mt], bh[j]);   // hh
                    mma16816(acc[mt][j], ah[mt], bl[j]);   // hl
                    mma16816(acc[mt][j], al[mt], bh[j]);   // lh
                }
        }
        __syncthreads();
    }

    const int g = lane >> 2;
    const int t = lane & 3;
    float* out = g_cv0 + (size_t)b * 8192 * 8192;
#pragma unroll
    for (int mt = 0; mt < 2; mt++) {
        const int mrow = m0 + wm + mt * 16 + g;
#pragma unroll
        for (int j = 0; j < 8; j++) {
            const int n = n0 + wn + j * 8 + 2 * t;
            float2 v0 = make_float2(acc[mt][j][0], acc[mt][j][1]);
            float2 v1 = make_float2(acc[mt][j][2], acc[mt][j][3]);
            *(float2*)&out[(size_t)mrow * 8192 + n] = v0;
            *(float2*)&out[(size_t)(mrow + 8) * 8192 + n] = v1;
        }
    }
}

// ---------------- kernel 2a: chunked KNN16 scan (all levels x 4 chunks) ------
// z = lvl*4 + chunk; each thread scans its chunk and writes sorted top-16
// (dist+idx) to scratch. Tie behavior: strict < insert keeps earliest index.
__global__ void __launch_bounds__(128) knn16_part(const float* __restrict__ xyz1,
                                                  const float* __restrict__ x0,
                                                  const float* __restrict__ x1,
                                                  const float* __restrict__ x2,
                                                  const float* __restrict__ x3)
{
    const int z = blockIdx.z;
    const int lvl = z >> 2, chunk = z & 3;
    const float* pxyz = (lvl == 0) ? x0 : (lvl == 1) ? x1 : (lvl == 2) ? x2 : x3;
    const int Ni      = (lvl == 0) ? 8192 : (lvl == 1) ? 2048 : (lvl == 2) ? 512 : 128;
    const int Nc = Ni >> 2;
    const int start = chunk * Nc;

    const int CH = 1024;
    __shared__ float sx[CH], sy[CH], sz[CH], sii[CH];
    const int b  = blockIdx.y;
    const int qi = blockIdx.x * 128 + threadIdx.x;

    const float qx = xyz1[(size_t)(b * 3 + 0) * N1 + qi];
    const float qy = xyz1[(size_t)(b * 3 + 1) * N1 + qi];
    const float qz = xyz1[(size_t)(b * 3 + 2) * N1 + qi];
    const float qq = qx * qx + qy * qy + qz * qz;

    float bd[16];
    int   bi[16];
#pragma unroll
    for (int j = 0; j < 16; j++) { bd[j] = 1e30f; bi[j] = 0; }

    for (int c0 = start; c0 < start + Nc; c0 += CH) {
        const int cnt = min(CH, start + Nc - c0);
        for (int t = threadIdx.x; t < cnt; t += 128) {
            const float ix = pxyz[(size_t)(b * 3 + 0) * Ni + c0 + t];
            const float iy = pxyz[(size_t)(b * 3 + 1) * Ni + c0 + t];
            const float iz = pxyz[(size_t)(b * 3 + 2) * Ni + c0 + t];
            sx[t] = ix; sy[t] = iy; sz[t] = iz;
            sii[t] = ix * ix + iy * iy + iz * iz;
        }
        __syncthreads();
#pragma unroll 4
        for (int t = 0; t < cnt; t++) {
            const float d = qq + sii[t]
                          - 2.0f * (qx * sx[t] + qy * sy[t] + qz * sz[t]);
            if (d < bd[15]) {
                bd[15] = d; bi[15] = c0 + t;
#pragma unroll
                for (int j = 15; j > 0; j--) {
                    if (bd[j] < bd[j - 1]) {
                        float td = bd[j]; bd[j] = bd[j - 1]; bd[j - 1] = td;
                        int   ti = bi[j]; bi[j] = bi[j - 1]; bi[j - 1] = ti;
                    }
                }
            }
        }
        __syncthreads();
    }

    const size_t base = (((size_t)lvl * 2 + b) * 8192 + qi) * 64 + chunk * 16;
#pragma unroll
    for (int j = 0; j < 16; j++) {
        g_scr_d[base + j] = bd[j];
        g_scr_i[base + j] = bi[j];
    }
}

// ---------------- kernel 2b: merge 4 sorted 16-lists -> top-16 ---------------
__global__ void __launch_bounds__(256) knn16_merge()
{
    const int g = blockIdx.x * 256 + threadIdx.x;   // 0 .. 4*2*8192-1
    const int lvl = g >> 14;
    const int rem = g & 16383;
    const int b = rem >> 13;
    const int qi = rem & 8191;

    const size_t base = (((size_t)lvl * 2 + b) * 8192 + qi) * 64;
    float bd[16];
    int   bi[16];
#pragma unroll
    for (int j = 0; j < 16; j++) { bd[j] = 1e30f; bi[j] = 0; }

    // chunks in ascending index order; strict < keeps earliest at ties
    for (int j = 0; j < 64; j++) {
        const float d = g_scr_d[base + j];
        const int   ii = g_scr_i[base + j];
        if (d < bd[15]) {
            bd[15] = d; bi[15] = ii;
#pragma unroll
            for (int k = 15; k > 0; k--) {
                if (bd[k] < bd[k - 1]) {
                    float td = bd[k]; bd[k] = bd[k - 1]; bd[k - 1] = td;
                    int   ti = bi[k]; bi[k] = bi[k - 1]; bi[k - 1] = ti;
                }
            }
        }
    }

    int* out = g_idx + (size_t)lvl * IDX_CROSS_STRIDE + ((size_t)b * N1 + qi) * 16;
#pragma unroll
    for (int j = 0; j < 16; j++) out[j] = bi[j];
}

// ---------------- kernel 2c: FUSED warp-per-query KNN3, all 3 levels ---------
__global__ void __launch_bounds__(256) knn3_all(const float* __restrict__ x0,
                                                const float* __restrict__ x1,
                                                const float* __restrict__ x2,
                                                const float* __restrict__ x3)
{
    const int l = blockIdx.z;
    const float* qxyz; const float* pxyz; int Nq, Ni, out_off;
    if (l == 0)      { qxyz = x1; pxyz = x0; Nq = 2048; Ni = 8192; out_off = IDX_PYR1; }
    else if (l == 1) { qxyz = x2; pxyz = x1; Nq = 512;  Ni = 2048; out_off = IDX_PYR2; }
    else             { qxyz = x3; pxyz = x2; Nq = 128;  Ni = 512;  out_off = IDX_PYR3; }
    if (blockIdx.x * 8 >= Nq) return;   // uniform per block: safe w.r.t. barriers

    const int CH = 2048;
    __shared__ float sx[CH], sy[CH], sz[CH];
    const int b    = blockIdx.y;
    const int w    = threadIdx.x >> 5;
    const int lane = threadIdx.x & 31;
    const int qi   = blockIdx.x * 8 + w;

    const float qx = qxyz[(size_t)(b * 3 + 0) * Nq + qi];
    const float qy = qxyz[(size_t)(b * 3 + 1) * Nq + qi];
    const float qz = qxyz[(size_t)(b * 3 + 2) * Nq + qi];
    const float qq = qx * qx + qy * qy + qz * qz;

    float bd[3];
    int   bi[3];
#pragma unroll
    for (int j = 0; j < 3; j++) { bd[j] = 1e30f; bi[j] = -(lane + 1); }

    for (int c0 = 0; c0 < Ni; c0 += CH) {
        const int cnt = min(CH, Ni - c0);
        __syncthreads();
        for (int t = threadIdx.x; t < cnt; t += 256) {
            sx[t] = pxyz[(size_t)(b * 3 + 0) * Ni + c0 + t];
            sy[t] = pxyz[(size_t)(b * 3 + 1) * Ni + c0 + t];
            sz[t] = pxyz[(size_t)(b * 3 + 2) * Ni + c0 + t];
        }
        __syncthreads();
        for (int t = lane; t < cnt; t += 32) {
            const float ix = sx[t], iy = sy[t], iz = sz[t];
            const float ii = ix * ix + iy * iy + iz * iz;
            const float d  = qq + ii - 2.0f * (qx * ix + qy * iy + qz * iz);
            if (d < bd[2]) {
                bd[2] = d; bi[2] = c0 + t;
#pragma unroll
                for (int j = 2; j > 0; j--) {
                    if (bd[j] < bd[j - 1]) {
                        float td = bd[j]; bd[j] = bd[j - 1]; bd[j - 1] = td;
                        int   ti = bi[j]; bi[j] = bi[j - 1]; bi[j - 1] = ti;
                    }
                }
            }
        }
    }

    int   p   = 0;
    float myd = bd[0];
    int   myi = bi[0];
    int   res = 0;
#pragma unroll
    for (int j = 0; j < 3; j++) {
        float d = myd; int ii = myi;
#pragma unroll
        for (int off = 16; off; off >>= 1) {
            float od = __shfl_xor_sync(0xFFFFFFFF, d, off);
            int   oi = __shfl_xor_sync(0xFFFFFFFF, ii, off);
            if (od < d || (od == d && oi < ii)) { d = od; ii = oi; }
        }
        if (lane == j) res = ii;
        if (myi == ii) {
            p++;
            if (p < 3) { myd = bd[p]; myi = bi[p]; }
            else       { myd = 1e30f; myi = -(lane + 33); }
        }
    }
    if (lane < 3)
        g_idx[out_off + ((size_t)b * Nq + qi) * 3 + lane] = res;
}

// ---------------- kernel 3: pyramid k=3 average (float4) ---------------------
__global__ void __launch_bounds__(256) pyr_avg(int lvl, int Nm, int Nprev, int idx_off)
{
    const float* prev = cv_ptr(lvl - 1);
    float* out        = cv_ptr(lvl);
    const int b = blockIdx.z;
    const int m = blockIdx.y;
    const int n4 = blockIdx.x * 256 + threadIdx.x;      // float4 index 0..2047
    const int* ip = g_idx + idx_off + ((size_t)b * Nm + m) * 3;
    const int i0 = ip[0], i1 = ip[1], i2 = ip[2];
    const float4 a = *(const float4*)&prev[(((size_t)b * Nprev + i0) * 8192) + n4 * 4];
    const float4 c = *(const float4*)&prev[(((size_t)b * Nprev + i1) * 8192) + n4 * 4];
    const float4 d = *(const float4*)&prev[(((size_t)b * Nprev + i2) * 8192) + n4 * 4];
    float4 v;
    v.x = (a.x + c.x + d.x) * (1.0f / 3.0f);
    v.y = (a.y + c.y + d.y) * (1.0f / 3.0f);
    v.z = (a.z + c.z + d.z) * (1.0f / 3.0f);
    v.w = (a.w + c.w + d.w) * (1.0f / 3.0f);
    *(float4*)&out[(((size_t)b * Nm + m) * 8192) + n4 * 4] = v;
}

// ---------------- kernel 4: FUSED per-level matching cost MLP ----------------
__global__ void __launch_bounds__(128) lc_all(const float* __restrict__ xyz1,
                                              const float* __restrict__ x0,
                                              const float* __restrict__ x1,
                                              const float* __restrict__ x2,
                                              const float* __restrict__ x3,
                                              const float* __restrict__ w1,
                                              const float* __restrict__ b1,
                                              const float* __restrict__ w2,
                                              const float* __restrict__ b2)
{
    __shared__ float sw1[64], sb1[16], sw2[256], sb2[16];
    const int t = threadIdx.x;
    if (t < 64) sw1[t] = w1[t];
    if (t < 16) sb1[t] = b1[t];
    for (int i = t; i < 256; i += 128) sw2[i] = w2[i];
    if (t >= 64 && t < 80) sb2[t - 64] = b2[t - 64];
    __syncthreads();

    const int lvl = blockIdx.z;
    const float* xyz2 = (lvl == 0) ? x0 : (lvl == 1) ? x1 : (lvl == 2) ? x2 : x3;
    const int Nl      = (lvl == 0) ? 8192 : (lvl == 1) ? 2048 : (lvl == 2) ? 512 : 128;

    const int b = blockIdx.y;
    const int n = blockIdx.x * 128 + t;
    const float* cvT = cv_ptr(lvl);
    const int* ip = g_idx + (size_t)lvl * IDX_CROSS_STRIDE + ((size_t)b * N1 + n) * 16;

    const float px = xyz1[(size_t)(b * 3 + 0) * N1 + n];
    const float py = xyz1[(size_t)(b * 3 + 1) * N1 + n];
    const float pz = xyz1[(size_t)(b * 3 + 2) * N1 + n];

    float acc[16];
#pragma unroll
    for (int o = 0; o < 16; o++) acc[o] = 0.0f;

#pragma unroll 4
    for (int k = 0; k < 16; k++) {
        const int i = ip[k];
        const float dx = xyz2[(size_t)(b * 3 + 0) * Nl + i] - px;
        const float dy = xyz2[(size_t)(b * 3 + 1) * Nl + i] - py;
        const float dz = xyz2[(size_t)(b * 3 + 2) * Nl + i] - pz;
        const float corr = cvT[((size_t)b * Nl + i) * 8192 + n];

        float h1[16];
#pragma unroll
        for (int o = 0; o < 16; o++) {
            float a = fmaf(sw1[o * 4 + 0], dx, sb1[o]);
            a = fmaf(sw1[o * 4 + 1], dy, a);
            a = fmaf(sw1[o * 4 + 2], dz, a);
            a = fmaf(sw1[o * 4 + 3], corr, a);
            h1[o] = fmaxf(a, 0.0f);
        }
#pragma unroll
        for (int o2 = 0; o2 < 16; o2++) {
            float a = sb2[o2];
#pragma unroll
            for (int o = 0; o < 16; o++) a = fmaf(sw2[o2 * 16 + o], h1[o], a);
            acc[o2] += fmaxf(a, 0.0f);
        }
    }
#pragma unroll
    for (int o2 = 0; o2 < 16; o2++)
        g_costs[((size_t)b * 64 + lvl * 16 + o2) * N1 + n] = acc[o2];
}

// ---------------- kernel 5: final 64x64 MLP ---------------------------------
__global__ void __launch_bounds__(256) final_mlp(const float* __restrict__ wm,
                                                 const float* __restrict__ bm,
                                                 float* __restrict__ out)
{
    __shared__ float swm[4096];
    __shared__ float sbm[64];
    const int t = threadIdx.x;
    for (int i = t; i < 4096; i += 256) swm[i] = wm[i];
    if (t < 64) sbm[t] = bm[t];
    __syncthreads();

    const int b = blockIdx.y;
    const int n = blockIdx.x * 256 + t;

    float c[64];
#pragma unroll
    for (int cc = 0; cc < 64; cc++)
        c[cc] = g_costs[((size_t)b * 64 + cc) * N1 + n];

#pragma unroll 4
    for (int o = 0; o < 64; o++) {
        float a = sbm[o];
#pragma unroll
        for (int cc = 0; cc < 64; cc++)
            a = fmaf(swm[o * 64 + cc], c[cc], a);
        out[((size_t)b * 64 + o) * N1 + n] = fmaxf(a, 0.0f);
    }
}

// ---------------- launcher ---------------------------------------------------
extern "C" void kernel_launch(void* const* d_in, const int* in_sizes, int n_in,
                              void* d_out, int out_size)
{
    const float* xyz1   = (const float*)d_in[0];
    const float* xyz2_0 = (const float*)d_in[1];
    const float* xyz2_1 = (const float*)d_in[2];
    const float* xyz2_2 = (const float*)d_in[3];
    const float* xyz2_3 = (const float*)d_in[4];
    const float* feat1  = (const float*)d_in[5];
    const float* feat2  = (const float*)d_in[6];
    const float* w1 = (const float*)d_in[7];
    const float* b1 = (const float*)d_in[8];
    const float* w2 = (const float*)d_in[9];
    const float* b2 = (const float*)d_in[10];
    const float* wm = (const float*)d_in[11];
    const float* bm = (const float*)d_in[12];
    float* out = (float*)d_out;

    static bool init = false;
    static cudaStream_t s1, s2;
    static cudaEvent_t ev0, evK3, evK16;
    if (!init) {
        cudaFuncSetAttribute(gemm_cv_mma, cudaFuncAttributeMaxDynamicSharedMemorySize,
                             GEMM_SMEM_BYTES);
        cudaStreamCreateWithFlags(&s1, cudaStreamNonBlocking);
        cudaStreamCreateWithFlags(&s2, cudaStreamNonBlocking);
        cudaEventCreateWithFlags(&ev0,  cudaEventDisableTiming);
        cudaEventCreateWithFlags(&evK3, cudaEventDisableTiming);
        cudaEventCreateWithFlags(&evK16, cudaEventDisableTiming);
        init = true;
    }

    // ---- fork: knn work runs concurrently with split+gemm ----
    cudaEventRecord(ev0, 0);
    cudaStreamWaitEvent(s1, ev0, 0);
    cudaStreamWaitEvent(s2, ev0, 0);

    // s1: pyramid KNN (all 3 levels fused)
    knn3_all<<<dim3(256, 2, 3), 256, 0, s1>>>(xyz2_0, xyz2_1, xyz2_2, xyz2_3);
    cudaEventRecord(evK3, s1);

    // s2: cross KNN chunked scan (4 levels x 4 chunks)
    knn16_part<<<dim3(64, 2, 16), 128, 0, s2>>>(xyz1, xyz2_0, xyz2_1, xyz2_2, xyz2_3);

    // default stream: split -> gemm (gemm stays the 4th launch for ncu)
    split_bf16<<<FEAT_ELEMS / 256, 256>>>(feat1, feat2);
    gemm_cv_mma<<<dim3(64, 64, 2), 256, GEMM_SMEM_BYTES>>>();

    // s2: merge chunk results -> final top-16 per query
    knn16_merge<<<256, 256, 0, s2>>>();
    cudaEventRecord(evK16, s2);

    // ---- join s1: pyramid averaging needs cv0 + pyramid knn ----
    cudaStreamWaitEvent(0, evK3, 0);
    pyr_avg<<<dim3(8, 2048, 2), 256>>>(1, 2048, 8192, IDX_PYR1);
    pyr_avg<<<dim3(8,  512, 2), 256>>>(2,  512, 2048, IDX_PYR2);
    pyr_avg<<<dim3(8,  128, 2), 256>>>(3,  128,  512, IDX_PYR3);

    // ---- join s2: matching cost needs cross knn + all cv levels ----
    cudaStreamWaitEvent(0, evK16, 0);
    lc_all<<<dim3(64, 2, 4), 128>>>(xyz1, xyz2_0, xyz2_1, xyz2_2, xyz2_3,
                                    w1, b1, w2, b2);

    // final MLP -> output [2][64][8192]
    final_mlp<<<dim3(32, 2), 256>>>(wm, bm, out);
}